// round 2
// baseline (speedup 1.0000x reference)
#include <cuda_runtime.h>
#include <math.h>

// Problem constants (fixed shapes)
#define BATCH 8
#define NPOS  4096      // h*w = 64*64
#define CCH   512
#define HEADS 8
#define DHEAD 64
#define HWDIM 64
#define KMAXH 128       // c/4, per spatial dim

// -------- scratch (device globals; no allocation allowed) --------
__device__ float g_qf[BATCH * NPOS * CCH];     // elu(q)+1   64 MB
__device__ float g_kf[BATCH * NPOS * CCH];     // elu(k)+1   64 MB
__device__ float g_cos[NPOS * (CCH / 2)];      // rope table 4 MB
__device__ float g_sin[NPOS * (CCH / 2)];      // rope table 4 MB
__device__ float g_kv[BATCH * HEADS * DHEAD * DHEAD];  // 256K elems
__device__ float g_ksum[BATCH * CCH];          // 4K elems

// -------- K0: zero accumulators (MUST cover all of g_kv: 262144 elems) ----
__global__ void zero_kernel() {
    int i = blockIdx.x * blockDim.x + threadIdx.x;
    if (i < BATCH * HEADS * DHEAD * DHEAD) g_kv[i] = 0.0f;
    if (i < BATCH * CCH) g_ksum[i] = 0.0f;
}

// -------- K0b: rope cos/sin table  (pos, jglobal) --------
__global__ void rope_table_kernel() {
    int pos = blockIdx.x;          // 0..4095
    int j   = threadIdx.x;         // 0..255
    int jm  = (j < KMAXH) ? j : (j - KMAXH);
    // theta_j = 10000^(-jm/128) = exp(-jm * ln(10000)/128)
    float theta = expf(-(float)jm * (9.210340371976184f / 128.0f));
    float coord = (j < KMAXH) ? (float)(pos >> 6) : (float)(pos & 63);
    float ang = coord * theta;
    float s, c;
    sincosf(ang, &s, &c);
    g_cos[pos * 256 + j] = c;
    g_sin[pos * 256 + j] = s;
}

// -------- K1: qk = x @ Wqk^T + bqk, then elu+1, split into g_qf / g_kf -----
// M=32768, N=1024, K=512. Both operands K-major (NT gemm).
// 128x128 block tile, BK=8, 256 threads, 8x8 per-thread microtile.
__global__ __launch_bounds__(256) void gemm_qk_kernel(
    const float* __restrict__ X,      // (32768, 512)
    const float* __restrict__ W,      // (1024, 512)
    const float* __restrict__ bias)   // (1024,)
{
    __shared__ float As[8][128];
    __shared__ float Bs[8][128];

    int bx = blockIdx.x;   // 0..7   (N tiles)
    int by = blockIdx.y;   // 0..255 (M tiles)
    int t  = threadIdx.x;
    int tx = t & 15;
    int ty = t >> 4;

    const float* Aptr = X + (size_t)(by * 128) * 512;
    const float* Bptr = W + (size_t)(bx * 128) * 512;

    int lr = t >> 1;        // 0..127
    int lc = (t & 1) * 4;   // 0 or 4

    float acc[8][8];
#pragma unroll
    for (int i = 0; i < 8; i++)
#pragma unroll
        for (int j = 0; j < 8; j++) acc[i][j] = 0.0f;

    for (int k0 = 0; k0 < 512; k0 += 8) {
        float4 av = *(const float4*)(Aptr + lr * 512 + k0 + lc);
        float4 bv = *(const float4*)(Bptr + lr * 512 + k0 + lc);
        As[lc + 0][lr] = av.x; As[lc + 1][lr] = av.y;
        As[lc + 2][lr] = av.z; As[lc + 3][lr] = av.w;
        Bs[lc + 0][lr] = bv.x; Bs[lc + 1][lr] = bv.y;
        Bs[lc + 2][lr] = bv.z; Bs[lc + 3][lr] = bv.w;
        __syncthreads();

#pragma unroll
        for (int kk = 0; kk < 8; kk++) {
            float a[8], b[8];
            *(float4*)(a)     = *(const float4*)&As[kk][ty * 8];
            *(float4*)(a + 4) = *(const float4*)&As[kk][ty * 8 + 4];
            *(float4*)(b)     = *(const float4*)&Bs[kk][tx * 8];
            *(float4*)(b + 4) = *(const float4*)&Bs[kk][tx * 8 + 4];
#pragma unroll
            for (int i = 0; i < 8; i++)
#pragma unroll
                for (int j = 0; j < 8; j++)
                    acc[i][j] = fmaf(a[i], b[j], acc[i][j]);
        }
        __syncthreads();
    }

    // epilogue: bias + (elu+1), split q/k
    int colBase = bx * 128 + tx * 8;
    int rowBase = by * 128 + ty * 8;
    bool isQ = (colBase < 512);
    float* dst = isQ ? g_qf : g_kf;
    int cb = isQ ? colBase : (colBase - 512);

    float bcol[8];
#pragma unroll
    for (int j = 0; j < 8; j++) bcol[j] = bias[colBase + j];

#pragma unroll
    for (int i = 0; i < 8; i++) {
        int row = rowBase + i;
        float* drow = dst + (size_t)row * 512 + cb;
#pragma unroll
        for (int j = 0; j < 8; j++) {
            float v = acc[i][j] + bcol[j];
            // elu(v)+1 = v>0 ? v+1 : exp(v)
            drow[j] = (v > 0.0f) ? (v + 1.0f) : expf(v);
        }
    }
}

// -------- K2: column sums of g_kf over n per batch --------
__global__ void ksum_kernel() {
    int blk = blockIdx.x;          // B*32 blocks
    int b = blk >> 5;
    int chunk = blk & 31;          // 128 rows each
    int ch = threadIdx.x;          // 512 threads
    const float* base = g_kf + ((size_t)(b * NPOS + chunk * 128)) * 512 + ch;
    float s = 0.0f;
    for (int r = 0; r < 128; r++) s += base[(size_t)r * 512];
    atomicAdd(&g_ksum[b * 512 + ch], s);
}

// -------- K3: kv[b,h,d,e] = (1/n) * sum_n rope(kf)[n,d] * x[n,e] --------
// grid: B*HEADS*8 (split-K over n, 512 rows each), 256 threads, 4x4 microtile
__global__ __launch_bounds__(256) void kv_kernel(const float* __restrict__ X) {
    __shared__ float ks[16 * 64];
    __shared__ float vs[16 * 64];

    int blk = blockIdx.x;
    int split = blk & 7;
    int head  = (blk >> 3) & 7;
    int b     = blk >> 6;
    int t  = threadIdx.x;
    int tx = t & 15;
    int ty = t >> 4;

    float acc[4][4];
#pragma unroll
    for (int i = 0; i < 4; i++)
#pragma unroll
        for (int j = 0; j < 4; j++) acc[i][j] = 0.0f;

    int n_base = split * 512;
    for (int c0 = 0; c0 < 512; c0 += 16) {
        int n0 = n_base + c0;
        // load 16x64 kf tile with rope applied (as float2 pairs)
#pragma unroll
        for (int rep = 0; rep < 2; rep++) {
            int p = t + rep * 256;      // 0..511 pair slots
            int row = p >> 5;
            int jl  = p & 31;
            int pos = n0 + row;
            float2 kv2 = *(const float2*)(g_kf +
                ((size_t)(b * NPOS + pos)) * 512 + head * 64 + 2 * jl);
            int jg = head * 32 + jl;
            float cc = g_cos[pos * 256 + jg];
            float ss = g_sin[pos * 256 + jg];
            ks[row * 64 + 2 * jl]     = cc * kv2.x - ss * kv2.y;
            ks[row * 64 + 2 * jl + 1] = cc * kv2.y + ss * kv2.x;
        }
        // load 16x64 x tile (v)
        {
            int row = t >> 4;
            int c4 = (t & 15) * 4;
            *(float4*)&vs[row * 64 + c4] = *(const float4*)(X +
                ((size_t)(b * NPOS + n0 + row)) * 512 + head * 64 + c4);
        }
        __syncthreads();

#pragma unroll
        for (int kk = 0; kk < 16; kk++) {
            float a[4], bb[4];
            *(float4*)a  = *(const float4*)&ks[kk * 64 + ty * 4];
            *(float4*)bb = *(const float4*)&vs[kk * 64 + tx * 4];
#pragma unroll
            for (int i = 0; i < 4; i++)
#pragma unroll
                for (int j = 0; j < 4; j++)
                    acc[i][j] = fmaf(a[i], bb[j], acc[i][j]);
        }
        __syncthreads();
    }

    float* kvp = g_kv + (b * 8 + head) * 4096;
#pragma unroll
    for (int i = 0; i < 4; i++)
#pragma unroll
        for (int j = 0; j < 4; j++)
            atomicAdd(&kvp[(ty * 4 + i) * 64 + tx * 4 + j],
                      acc[i][j] * (1.0f / 4096.0f));
}

// -------- K4: out = (rope(q) @ kv) * z,  z = 1/(q . kmean + 1e-6) --------
// grid: B*HEADS*64 blocks (64 positions each), 256 threads
__global__ __launch_bounds__(256) void out_kernel(float* __restrict__ out) {
    __shared__ float kvs[64 * 64];
    __shared__ float qs[64 * 65];   // padded row stride (scalar access only)
    __shared__ float zarr[64];
    __shared__ float km[64];

    int blk = blockIdx.x;
    int pchunk = blk & 63;
    int head   = (blk >> 6) & 7;
    int b      = blk >> 9;
    int n0 = pchunk * 64;
    int t = threadIdx.x;

    const float* kvp = g_kv + (b * 8 + head) * 4096;
    for (int i = t; i < 4096; i += 256) kvs[i] = kvp[i];
    if (t < 64) km[t] = g_ksum[b * 512 + head * 64 + t] * (1.0f / 4096.0f);

    // load raw q tile (64 pos x 64 ch)
    {
        int pos = t >> 2;
        int cb = (t & 3) * 16;
        const float* src = g_qf + ((size_t)(b * NPOS + n0 + pos)) * 512 + head * 64 + cb;
        float* dq = &qs[pos * 65 + cb];
#pragma unroll
        for (int u = 0; u < 16; u += 4) {
            float4 v = *(const float4*)(src + u);
            dq[u + 0] = v.x; dq[u + 1] = v.y; dq[u + 2] = v.z; dq[u + 3] = v.w;
        }
    }
    __syncthreads();

    // z from raw q
    if (t < 64) {
        float dot = 0.0f;
#pragma unroll
        for (int d2 = 0; d2 < 64; d2++) dot = fmaf(qs[t * 65 + d2], km[d2], dot);
        zarr[t] = 1.0f / (dot + 1e-6f);
    }
    __syncthreads();

    // rope q in place
#pragma unroll
    for (int rep = 0; rep < 8; rep++) {
        int p = t + rep * 256;   // 0..2047 pairs
        int pos = p >> 5;
        int jl  = p & 31;
        float re = qs[pos * 65 + 2 * jl];
        float im = qs[pos * 65 + 2 * jl + 1];
        int gp = (n0 + pos) * 256 + head * 32 + jl;
        float cc = g_cos[gp];
        float ss = g_sin[gp];
        qs[pos * 65 + 2 * jl]     = cc * re - ss * im;
        qs[pos * 65 + 2 * jl + 1] = cc * im + ss * re;
    }
    __syncthreads();

    // matvec: 4 positions in parallel, 64 e-threads each
    int e = t & 63;
    for (int it = 0; it < 16; it++) {
        int pos = it * 4 + (t >> 6);
        float a2 = 0.0f;
#pragma unroll
        for (int d2 = 0; d2 < 64; d2++)
            a2 = fmaf(qs[pos * 65 + d2], kvs[d2 * 64 + e], a2);
        out[((size_t)(b * NPOS + n0 + pos)) * 512 + head * 64 + e] = a2 * zarr[pos];
    }
}

// -------- K5: LePE depthwise 3x3 conv on x, added into out --------
__global__ void lepe_kernel(const float* __restrict__ X,
                            const float* __restrict__ Wc,
                            const float* __restrict__ Bc,
                            float* __restrict__ out) {
    int idx = blockIdx.x * blockDim.x + threadIdx.x;   // 16.7M threads
    int ch  = idx & 511;
    int rest = idx >> 9;
    int pos = rest & 4095;
    int b = rest >> 12;
    int hi = pos >> 6;
    int wi = pos & 63;

    float acc = Bc[ch];
    const float* wp = Wc + ch * 9;
    const float* xb = X + ((size_t)b * NPOS) * 512 + ch;
#pragma unroll
    for (int ky = 0; ky < 3; ky++) {
        int y = hi + ky - 1;
        if ((unsigned)y >= 64u) continue;
#pragma unroll
        for (int kx = 0; kx < 3; kx++) {
            int xw = wi + kx - 1;
            if ((unsigned)xw >= 64u) continue;
            acc = fmaf(xb[((size_t)(y * 64 + xw)) * 512], wp[ky * 3 + kx], acc);
        }
    }
    out[idx] += acc;
}

// -------- launch --------
extern "C" void kernel_launch(void* const* d_in, const int* in_sizes, int n_in,
                              void* d_out, int out_size) {
    const float* x   = nullptr;
    const float* Wqk = nullptr;
    const float* bqk = nullptr;
    const float* lw  = nullptr;
    const float* lb  = nullptr;
    for (int i = 0; i < n_in; i++) {
        switch (in_sizes[i]) {
            case 16777216: x   = (const float*)d_in[i]; break;  // x (8,4096,512)
            case 524288:   Wqk = (const float*)d_in[i]; break;  // (1024,512)
            case 1024:     bqk = (const float*)d_in[i]; break;
            case 4608:     lw  = (const float*)d_in[i]; break;  // (512,1,3,3)
            case 512:      lb  = (const float*)d_in[i]; break;
            default: break; // scalar h, w (size 1) ignored; shapes are fixed
        }
    }
    float* out = (float*)d_out;

    // 262144 kv elements -> 1024 blocks x 256 threads (this was the R1 bug)
    zero_kernel<<<1024, 256>>>();
    rope_table_kernel<<<NPOS, 256>>>();
    gemm_qk_kernel<<<dim3(8, 256), 256>>>(x, Wqk, bqk);
    ksum_kernel<<<BATCH * 32, 512>>>();
    kv_kernel<<<BATCH * HEADS * 8, 256>>>(x);
    out_kernel<<<BATCH * HEADS * 64, 256>>>(out);
    lepe_kernel<<<(BATCH * NPOS * CCH) / 256, 256>>>(x, lw, lb, out);
}

// round 4
// speedup vs baseline: 1.6843x; 1.6843x over previous
#include <cuda_runtime.h>
#include <math.h>
#include <stdint.h>

// Problem constants (fixed shapes)
#define BATCH 8
#define NPOS  4096      // h*w = 64*64
#define CCH   512
#define HEADS 8
#define DHEAD 64
#define HWDIM 64
#define KMAXH 128       // c/4, per spatial dim

// -------- scratch (device globals; no allocation allowed) --------
__device__ float g_qf[BATCH * NPOS * CCH];     // elu(q)+1   64 MB
__device__ float g_kf[BATCH * NPOS * CCH];     // elu(k)+1   64 MB
__device__ float g_cos[NPOS * (CCH / 2)];      // rope table 4 MB
__device__ float g_sin[NPOS * (CCH / 2)];      // rope table 4 MB
__device__ float g_kv[BATCH * HEADS * DHEAD * DHEAD];  // 256K elems
__device__ float g_ksum[BATCH * CCH];          // 4K elems

// -------- K0: zero accumulators (covers g_kv: 262144 elems) ----
__global__ void zero_kernel() {
    int i = blockIdx.x * blockDim.x + threadIdx.x;
    if (i < BATCH * HEADS * DHEAD * DHEAD) g_kv[i] = 0.0f;
    if (i < BATCH * CCH) g_ksum[i] = 0.0f;
}

// -------- K0b: rope cos/sin table  (pos, jglobal) --------
__global__ void rope_table_kernel() {
    int pos = blockIdx.x;          // 0..4095
    int j   = threadIdx.x;         // 0..255
    int jm  = (j < KMAXH) ? j : (j - KMAXH);
    float theta = expf(-(float)jm * (9.210340371976184f / 128.0f));
    float coord = (j < KMAXH) ? (float)(pos >> 6) : (float)(pos & 63);
    float ang = coord * theta;
    float s, c;
    sincosf(ang, &s, &c);
    g_cos[pos * 256 + j] = c;
    g_sin[pos * 256 + j] = s;
}

// ---------------- TF32 tensor-core GEMM ----------------
// qk = X @ W^T + b, elu+1, split into g_qf/g_kf.
// M=32768, N=1024, K=512. Block 128x128, BK=32, 256 thr, warp tile 64x32.
// smem permuted so mma fragments load as LDS.128 (A) / LDS.64 (B).

__device__ __forceinline__ uint32_t f2tf32(float x) {
    uint32_t r;
    asm("cvt.rna.tf32.f32 %0, %1;" : "=r"(r) : "f"(x));
    return r;
}

__device__ __forceinline__ void mma_tf32(float* c, const uint32_t* a, const uint32_t* b) {
    asm volatile(
        "mma.sync.aligned.m16n8k8.row.col.f32.tf32.tf32.f32 "
        "{%0,%1,%2,%3}, {%4,%5,%6,%7}, {%8,%9}, {%0,%1,%2,%3};\n"
        : "+f"(c[0]), "+f"(c[1]), "+f"(c[2]), "+f"(c[3])
        : "r"(a[0]), "r"(a[1]), "r"(a[2]), "r"(a[3]),
          "r"(b[0]), "r"(b[1]));
}

__global__ __launch_bounds__(256) void gemm_qk_tf32_kernel(
    const float* __restrict__ X,      // (32768, 512)
    const float* __restrict__ W,      // (1024, 512)
    const float* __restrict__ bias)   // (1024,)
{
    // A: [kstep(4)][mtile(8)][lane(32)][reg(4)]  — frag layout of m16n8k8 tf32
    // B: [kstep(4)][ntile(16)][lane(32)][reg(2)]
    __shared__ uint32_t As[4][8][32][4];
    __shared__ uint32_t Bs[4][16][32][2];

    const int bx = blockIdx.x;   // 0..7   N tiles (bx<4 -> q, else k)
    const int by = blockIdx.y;   // 0..255 M tiles
    const int tid = threadIdx.x;
    const int lane = tid & 31;
    const int warp = tid >> 5;
    const int wm = warp >> 2;    // 0..1
    const int wn = warp & 3;     // 0..3

    // gmem load assignment: pass p -> row = p*32 + tid/8, c4 = (tid%8)*4
    const int lrow = tid >> 3;
    const int lc4  = (tid & 7) * 4;

    const float* Aptr = X + (size_t)(by * 128) * 512;
    const float* Bptr = W + (size_t)(bx * 128) * 512;

    float acc[4][4][4];
#pragma unroll
    for (int i = 0; i < 4; i++)
#pragma unroll
        for (int j = 0; j < 4; j++)
#pragma unroll
            for (int r = 0; r < 4; r++) acc[i][j][r] = 0.0f;

    // precomputed store indices (constant across iters)
    const int ksA  = lc4 >> 3;
    const int regA_hi = 2 * ((lc4 & 7) >> 2);
    const int regB = (lc4 & 7) >> 2;

    float4 av[4], bv[4];
    // prefetch iter 0
#pragma unroll
    for (int p = 0; p < 4; p++) {
        int row = p * 32 + lrow;
        av[p] = *(const float4*)(Aptr + (size_t)row * 512 + lc4);
        bv[p] = *(const float4*)(Bptr + (size_t)row * 512 + lc4);
    }

    for (int iter = 0; iter < 16; iter++) {
        __syncthreads();   // previous compute done before overwriting smem
        // store prefetched tile with tf32 convert + fragment permutation
#pragma unroll
        for (int p = 0; p < 4; p++) {
            int row = p * 32 + lrow;
            int mtile = row >> 4;
            int rr = row & 15;
            int laneA = (rr & 7) * 4;
            int regA = (rr >> 3) + regA_hi;
            float va[4] = {av[p].x, av[p].y, av[p].z, av[p].w};
#pragma unroll
            for (int j = 0; j < 4; j++)
                As[ksA][mtile][laneA + j][regA] = f2tf32(va[j]);

            int ntile = row >> 3;
            int laneB = (row & 7) * 4;
            float vb[4] = {bv[p].x, bv[p].y, bv[p].z, bv[p].w};
#pragma unroll
            for (int j = 0; j < 4; j++)
                Bs[ksA][ntile][laneB + j][regB] = f2tf32(vb[j]);
        }
        __syncthreads();

        // prefetch next tile
        if (iter + 1 < 16) {
            int k0 = (iter + 1) * 32;
#pragma unroll
            for (int p = 0; p < 4; p++) {
                int row = p * 32 + lrow;
                av[p] = *(const float4*)(Aptr + (size_t)row * 512 + k0 + lc4);
                bv[p] = *(const float4*)(Bptr + (size_t)row * 512 + k0 + lc4);
            }
        }

        // compute: 4 ksteps x (4 mtiles x 4 ntiles) mma
#pragma unroll
        for (int ks = 0; ks < 4; ks++) {
            uint4 af[4];
            uint2 bf[4];
#pragma unroll
            for (int i = 0; i < 4; i++)
                af[i] = *(const uint4*)&As[ks][wm * 4 + i][lane][0];
#pragma unroll
            for (int j = 0; j < 4; j++)
                bf[j] = *(const uint2*)&Bs[ks][wn * 4 + j][lane][0];
#pragma unroll
            for (int i = 0; i < 4; i++)
#pragma unroll
                for (int j = 0; j < 4; j++)
                    mma_tf32(acc[i][j], (const uint32_t*)&af[i], (const uint32_t*)&bf[j]);
        }
    }

    // epilogue: bias + elu+1, split q/k.
    // c layout: c0:(g, 2t) c1:(g, 2t+1) c2:(g+8, 2t) c3:(g+8, 2t+1)
    const int g = lane >> 2;
    const int t4 = lane & 3;
    const bool isQ = (bx < 4);
    float* dst = isQ ? g_qf : g_kf;

#pragma unroll
    for (int i = 0; i < 4; i++) {
        int r0 = by * 128 + wm * 64 + i * 16 + g;
#pragma unroll
        for (int j = 0; j < 4; j++) {
            int cg = bx * 128 + wn * 32 + j * 8 + 2 * t4;
            int cb = cg & 511;
            float b0 = bias[cg], b1 = bias[cg + 1];
            float v00 = acc[i][j][0] + b0;
            float v01 = acc[i][j][1] + b1;
            float v10 = acc[i][j][2] + b0;
            float v11 = acc[i][j][3] + b1;
            float2 o0, o1;
            o0.x = (v00 > 0.0f) ? (v00 + 1.0f) : expf(v00);
            o0.y = (v01 > 0.0f) ? (v01 + 1.0f) : expf(v01);
            o1.x = (v10 > 0.0f) ? (v10 + 1.0f) : expf(v10);
            o1.y = (v11 > 0.0f) ? (v11 + 1.0f) : expf(v11);
            *(float2*)&dst[(size_t)r0 * 512 + cb] = o0;
            *(float2*)&dst[(size_t)(r0 + 8) * 512 + cb] = o1;
        }
    }
}

// -------- K2: column sums of g_kf over n per batch --------
__global__ void ksum_kernel() {
    int blk = blockIdx.x;          // B*32 blocks
    int b = blk >> 5;
    int chunk = blk & 31;          // 128 rows each
    int ch = threadIdx.x;          // 512 threads
    const float* base = g_kf + ((size_t)(b * NPOS + chunk * 128)) * 512 + ch;
    float s = 0.0f;
    for (int r = 0; r < 128; r++) s += base[(size_t)r * 512];
    atomicAdd(&g_ksum[b * 512 + ch], s);
}

// -------- K3: kv[b,h,d,e] = (1/n) * sum_n rope(kf)[n,d] * x[n,e] --------
__global__ __launch_bounds__(256) void kv_kernel(const float* __restrict__ X) {
    __shared__ float ks[16 * 64];
    __shared__ float vs[16 * 64];

    int blk = blockIdx.x;
    int split = blk & 7;
    int head  = (blk >> 3) & 7;
    int b     = blk >> 6;
    int t  = threadIdx.x;
    int tx = t & 15;
    int ty = t >> 4;

    float acc[4][4];
#pragma unroll
    for (int i = 0; i < 4; i++)
#pragma unroll
        for (int j = 0; j < 4; j++) acc[i][j] = 0.0f;

    int n_base = split * 512;
    for (int c0 = 0; c0 < 512; c0 += 16) {
        int n0 = n_base + c0;
#pragma unroll
        for (int rep = 0; rep < 2; rep++) {
            int p = t + rep * 256;
            int row = p >> 5;
            int jl  = p & 31;
            int pos = n0 + row;
            float2 kv2 = *(const float2*)(g_kf +
                ((size_t)(b * NPOS + pos)) * 512 + head * 64 + 2 * jl);
            int jg = head * 32 + jl;
            float cc = g_cos[pos * 256 + jg];
            float ss = g_sin[pos * 256 + jg];
            ks[row * 64 + 2 * jl]     = cc * kv2.x - ss * kv2.y;
            ks[row * 64 + 2 * jl + 1] = cc * kv2.y + ss * kv2.x;
        }
        {
            int row = t >> 4;
            int c4 = (t & 15) * 4;
            *(float4*)&vs[row * 64 + c4] = *(const float4*)(X +
                ((size_t)(b * NPOS + n0 + row)) * 512 + head * 64 + c4);
        }
        __syncthreads();

#pragma unroll
        for (int kk = 0; kk < 16; kk++) {
            float a[4], bb[4];
            *(float4*)a  = *(const float4*)&ks[kk * 64 + ty * 4];
            *(float4*)bb = *(const float4*)&vs[kk * 64 + tx * 4];
#pragma unroll
            for (int i = 0; i < 4; i++)
#pragma unroll
                for (int j = 0; j < 4; j++)
                    acc[i][j] = fmaf(a[i], bb[j], acc[i][j]);
        }
        __syncthreads();
    }

    float* kvp = g_kv + (b * 8 + head) * 4096;
#pragma unroll
    for (int i = 0; i < 4; i++)
#pragma unroll
        for (int j = 0; j < 4; j++)
            atomicAdd(&kvp[(ty * 4 + i) * 64 + tx * 4 + j],
                      acc[i][j] * (1.0f / 4096.0f));
}

// -------- K4: out = (rope(q) @ kv) * z,  z = 1/(q . kmean + 1e-6) --------
__global__ __launch_bounds__(256) void out_kernel(float* __restrict__ out) {
    __shared__ float kvs[64 * 64];
    __shared__ float qs[64 * 65];
    __shared__ float zarr[64];
    __shared__ float km[64];

    int blk = blockIdx.x;
    int pchunk = blk & 63;
    int head   = (blk >> 6) & 7;
    int b      = blk >> 9;
    int n0 = pchunk * 64;
    int t = threadIdx.x;

    const float* kvp = g_kv + (b * 8 + head) * 4096;
    for (int i = t; i < 4096; i += 256) kvs[i] = kvp[i];
    if (t < 64) km[t] = g_ksum[b * 512 + head * 64 + t] * (1.0f / 4096.0f);

    {
        int pos = t >> 2;
        int cb = (t & 3) * 16;
        const float* src = g_qf + ((size_t)(b * NPOS + n0 + pos)) * 512 + head * 64 + cb;
        float* dq = &qs[pos * 65 + cb];
#pragma unroll
        for (int u = 0; u < 16; u += 4) {
            float4 v = *(const float4*)(src + u);
            dq[u + 0] = v.x; dq[u + 1] = v.y; dq[u + 2] = v.z; dq[u + 3] = v.w;
        }
    }
    __syncthreads();

    if (t < 64) {
        float dot = 0.0f;
#pragma unroll
        for (int d2 = 0; d2 < 64; d2++) dot = fmaf(qs[t * 65 + d2], km[d2], dot);
        zarr[t] = 1.0f / (dot + 1e-6f);
    }
    __syncthreads();

#pragma unroll
    for (int rep = 0; rep < 8; rep++) {
        int p = t + rep * 256;
        int pos = p >> 5;
        int jl  = p & 31;
        float re = qs[pos * 65 + 2 * jl];
        float im = qs[pos * 65 + 2 * jl + 1];
        int gp = (n0 + pos) * 256 + head * 32 + jl;
        float cc = g_cos[gp];
        float ss = g_sin[gp];
        qs[pos * 65 + 2 * jl]     = cc * re - ss * im;
        qs[pos * 65 + 2 * jl + 1] = cc * im + ss * re;
    }
    __syncthreads();

    int e = t & 63;
    for (int it = 0; it < 16; it++) {
        int pos = it * 4 + (t >> 6);
        float a2 = 0.0f;
#pragma unroll
        for (int d2 = 0; d2 < 64; d2++)
            a2 = fmaf(qs[pos * 65 + d2], kvs[d2 * 64 + e], a2);
        out[((size_t)(b * NPOS + n0 + pos)) * 512 + head * 64 + e] = a2 * zarr[pos];
    }
}

// -------- K5: LePE depthwise 3x3 conv on x, added into out --------
__global__ void lepe_kernel(const float* __restrict__ X,
                            const float* __restrict__ Wc,
                            const float* __restrict__ Bc,
                            float* __restrict__ out) {
    int idx = blockIdx.x * blockDim.x + threadIdx.x;
    int ch  = idx & 511;
    int rest = idx >> 9;
    int pos = rest & 4095;
    int b = rest >> 12;
    int hi = pos >> 6;
    int wi = pos & 63;

    float acc = Bc[ch];
    const float* wp = Wc + ch * 9;
    const float* xb = X + ((size_t)b * NPOS) * 512 + ch;
#pragma unroll
    for (int ky = 0; ky < 3; ky++) {
        int y = hi + ky - 1;
        if ((unsigned)y >= 64u) continue;
#pragma unroll
        for (int kx = 0; kx < 3; kx++) {
            int xw = wi + kx - 1;
            if ((unsigned)xw >= 64u) continue;
            acc = fmaf(xb[((size_t)(y * 64 + xw)) * 512], wp[ky * 3 + kx], acc);
        }
    }
    out[idx] += acc;
}

// -------- launch --------
extern "C" void kernel_launch(void* const* d_in, const int* in_sizes, int n_in,
                              void* d_out, int out_size) {
    const float* x   = nullptr;
    const float* Wqk = nullptr;
    const float* bqk = nullptr;
    const float* lw  = nullptr;
    const float* lb  = nullptr;
    for (int i = 0; i < n_in; i++) {
        switch (in_sizes[i]) {
            case 16777216: x   = (const float*)d_in[i]; break;  // x (8,4096,512)
            case 524288:   Wqk = (const float*)d_in[i]; break;  // (1024,512)
            case 1024:     bqk = (const float*)d_in[i]; break;
            case 4608:     lw  = (const float*)d_in[i]; break;  // (512,1,3,3)
            case 512:      lb  = (const float*)d_in[i]; break;
            default: break;
        }
    }
    float* out = (float*)d_out;

    zero_kernel<<<1024, 256>>>();
    rope_table_kernel<<<NPOS, 256>>>();
    gemm_qk_tf32_kernel<<<dim3(8, 256), 256>>>(x, Wqk, bqk);
    ksum_kernel<<<BATCH * 32, 512>>>();
    kv_kernel<<<BATCH * HEADS * 8, 256>>>(x);
    out_kernel<<<BATCH * HEADS * 64, 256>>>(out);
    lepe_kernel<<<(BATCH * NPOS * CCH) / 256, 256>>>(x, lw, lb, out);
}

// round 7
// speedup vs baseline: 2.2994x; 1.3652x over previous
#include <cuda_runtime.h>
#include <math.h>
#include <stdint.h>

// Problem constants (fixed shapes)
#define BATCH 8
#define NPOS  4096      // h*w = 64*64
#define CCH   512
#define HEADS 8
#define DHEAD 64
#define KMAXH 128       // c/4, per spatial dim

// -------- scratch (device globals; no allocation allowed) --------
__device__ float g_qf[BATCH * NPOS * CCH];     // elu(q)+1   64 MB
__device__ float g_kf[BATCH * NPOS * CCH];     // elu(k)+1   64 MB
__device__ float g_cos[NPOS * (CCH / 2)];      // rope table 4 MB
__device__ float g_sin[NPOS * (CCH / 2)];      // rope table 4 MB
__device__ float g_kv[BATCH * HEADS * DHEAD * DHEAD];  // 256K elems
__device__ float g_ksum[BATCH * CCH];          // 4K elems

// -------- K0: zero accumulators (covers g_kv: 262144 elems) ----
__global__ void zero_kernel() {
    int i = blockIdx.x * blockDim.x + threadIdx.x;
    if (i < BATCH * HEADS * DHEAD * DHEAD) g_kv[i] = 0.0f;
    if (i < BATCH * CCH) g_ksum[i] = 0.0f;
}

// -------- K0b: rope cos/sin table --------
__global__ void rope_table_kernel() {
    int pos = blockIdx.x;          // 0..4095
    int j   = threadIdx.x;         // 0..255
    int jm  = (j < KMAXH) ? j : (j - KMAXH);
    float theta = expf(-(float)jm * (9.210340371976184f / 128.0f));
    float coord = (j < KMAXH) ? (float)(pos >> 6) : (float)(pos & 63);
    float ang = coord * theta;
    float s, c;
    sincosf(ang, &s, &c);
    g_cos[pos * 256 + j] = c;
    g_sin[pos * 256 + j] = s;
}

// ---------------- BF16 tensor-core GEMM (legacy mma.sync) ----------------
// qk = X @ W^T + b, elu+1, split into g_qf/g_kf.
// M=32768, N=1024, K=512. Block 128x128, BK=32, 256 thr, warp tile 64x32.
// smem holds fragments pre-permuted: A frag = one LDS.128, B frag = one LDS.64.

__device__ __forceinline__ uint32_t pack_bf16x2(float lo, float hi) {
    uint32_t r;
    asm("cvt.rn.bf16x2.f32 %0, %1, %2;" : "=r"(r) : "f"(hi), "f"(lo));
    return r;
}

__device__ __forceinline__ void mma_bf16(float* c, const uint32_t* a, const uint32_t* b) {
    asm volatile(
        "mma.sync.aligned.m16n8k16.row.col.f32.bf16.bf16.f32 "
        "{%0,%1,%2,%3}, {%4,%5,%6,%7}, {%8,%9}, {%0,%1,%2,%3};\n"
        : "+f"(c[0]), "+f"(c[1]), "+f"(c[2]), "+f"(c[3])
        : "r"(a[0]), "r"(a[1]), "r"(a[2]), "r"(a[3]),
          "r"(b[0]), "r"(b[1]));
}

__global__ __launch_bounds__(256) void gemm_qk_bf16_kernel(
    const float* __restrict__ X,      // (32768, 512)
    const float* __restrict__ W,      // (1024, 512)
    const float* __restrict__ bias)   // (1024,)
{
    // m16n8k16 bf16 fragment stores:
    // A: [kstep(2)][mtile(8)][lane(32)][reg(4)]   reg = uint32 (2 bf16 along k)
    // B: [kstep(2)][ntile(16)][lane(32)][reg(2)]
    __shared__ uint32_t As[2][8][32][4];
    __shared__ uint32_t Bs[2][16][32][2];

    const int bx = blockIdx.x;   // 0..7   N tiles (bx<4 -> q, else k)
    const int by = blockIdx.y;   // 0..255 M tiles
    const int tid = threadIdx.x;
    const int lane = tid & 31;
    const int warp = tid >> 5;
    const int wm = warp >> 2;    // 0..1
    const int wn = warp & 3;     // 0..3

    // gmem load: pass p -> row = p*32 + tid/8, c4 = (tid%8)*4  (BK=32)
    const int lrow = tid >> 3;
    const int lc4  = (tid & 7) * 4;

    const float* Aptr = X + (size_t)(by * 128) * 512;
    const float* Bptr = W + (size_t)(bx * 128) * 512;

    float acc[4][4][4];
#pragma unroll
    for (int i = 0; i < 4; i++)
#pragma unroll
        for (int j = 0; j < 4; j++)
#pragma unroll
            for (int r = 0; r < 4; r++) acc[i][j][r] = 0.0f;

    // word kp-index helpers (constant per thread):
    // kp = lc4/2 + w (w=0,1); kstep = kp>>3; kp8 = kp&7; tig = kp8&3; hi = kp8>>2
    const int kp0   = lc4 >> 1;
    const int ks_w[2]  = { (kp0 + 0) >> 3, (kp0 + 1) >> 3 };
    const int tig_w[2] = { (kp0 + 0) & 3,  (kp0 + 1) & 3 };
    const int hi_w[2]  = { ((kp0 + 0) & 7) >> 2, ((kp0 + 1) & 7) >> 2 };

    float4 av[4], bv[4];
#pragma unroll
    for (int p = 0; p < 4; p++) {
        int row = p * 32 + lrow;
        av[p] = *(const float4*)(Aptr + (size_t)row * 512 + lc4);
        bv[p] = *(const float4*)(Bptr + (size_t)row * 512 + lc4);
    }

    for (int iter = 0; iter < 16; iter++) {
        __syncthreads();
#pragma unroll
        for (int p = 0; p < 4; p++) {
            int row = p * 32 + lrow;
            // ---- A fragment store ----
            int mtile = row >> 4;
            int rA = row & 15;
            int gA = rA & 7;
            int rowhi = rA >> 3;
            float va[4] = {av[p].x, av[p].y, av[p].z, av[p].w};
#pragma unroll
            for (int w = 0; w < 2; w++) {
                uint32_t word = pack_bf16x2(va[2 * w], va[2 * w + 1]);
                As[ks_w[w]][mtile][gA * 4 + tig_w[w]][hi_w[w] * 2 + rowhi] = word;
            }
            // ---- B fragment store ----
            int ntile = row >> 3;
            int gB = row & 7;
            float vb[4] = {bv[p].x, bv[p].y, bv[p].z, bv[p].w};
#pragma unroll
            for (int w = 0; w < 2; w++) {
                uint32_t word = pack_bf16x2(vb[2 * w], vb[2 * w + 1]);
                Bs[ks_w[w]][ntile][gB * 4 + tig_w[w]][hi_w[w]] = word;
            }
        }
        __syncthreads();

        if (iter + 1 < 16) {
            int k0 = (iter + 1) * 32;
#pragma unroll
            for (int p = 0; p < 4; p++) {
                int row = p * 32 + lrow;
                av[p] = *(const float4*)(Aptr + (size_t)row * 512 + k0 + lc4);
                bv[p] = *(const float4*)(Bptr + (size_t)row * 512 + k0 + lc4);
            }
        }

#pragma unroll
        for (int ks = 0; ks < 2; ks++) {
            uint4 af[4];
            uint2 bf[4];
#pragma unroll
            for (int i = 0; i < 4; i++)
                af[i] = *(const uint4*)&As[ks][wm * 4 + i][lane][0];
#pragma unroll
            for (int j = 0; j < 4; j++)
                bf[j] = *(const uint2*)&Bs[ks][wn * 4 + j][lane][0];
#pragma unroll
            for (int i = 0; i < 4; i++)
#pragma unroll
                for (int j = 0; j < 4; j++)
                    mma_bf16(acc[i][j], (const uint32_t*)&af[i], (const uint32_t*)&bf[j]);
        }
    }

    // epilogue: bias + elu+1, split q/k.
    // c layout: c0:(g, 2t) c1:(g, 2t+1) c2:(g+8, 2t) c3:(g+8, 2t+1)
    const int g = lane >> 2;
    const int t4 = lane & 3;
    const bool isQ = (bx < 4);
    float* dst = isQ ? g_qf : g_kf;

#pragma unroll
    for (int i = 0; i < 4; i++) {
        int r0 = by * 128 + wm * 64 + i * 16 + g;
#pragma unroll
        for (int j = 0; j < 4; j++) {
            int cg = bx * 128 + wn * 32 + j * 8 + 2 * t4;
            int cb = cg & 511;
            float b0 = bias[cg], b1 = bias[cg + 1];
            float v00 = acc[i][j][0] + b0;
            float v01 = acc[i][j][1] + b1;
            float v10 = acc[i][j][2] + b0;
            float v11 = acc[i][j][3] + b1;
            float2 o0, o1;
            o0.x = (v00 > 0.0f) ? (v00 + 1.0f) : expf(v00);
            o0.y = (v01 > 0.0f) ? (v01 + 1.0f) : expf(v01);
            o1.x = (v10 > 0.0f) ? (v10 + 1.0f) : expf(v10);
            o1.y = (v11 > 0.0f) ? (v11 + 1.0f) : expf(v11);
            *(float2*)&dst[(size_t)r0 * 512 + cb] = o0;
            *(float2*)&dst[(size_t)(r0 + 8) * 512 + cb] = o1;
        }
    }
}

// -------- K2: column sums of g_kf over n per batch --------
__global__ void ksum_kernel() {
    int blk = blockIdx.x;          // B*32 blocks
    int b = blk >> 5;
    int chunk = blk & 31;          // 128 rows each
    int ch = threadIdx.x;          // 512 threads
    const float* base = g_kf + ((size_t)(b * NPOS + chunk * 128)) * 512 + ch;
    float s = 0.0f;
    for (int r = 0; r < 128; r++) s += base[(size_t)r * 512];
    atomicAdd(&g_ksum[b * 512 + ch], s);
}

// -------- K3: kv[b,h,d,e] = (1/n) * sum_n rope(kf)[n,d] * x[n,e] --------
__global__ __launch_bounds__(256) void kv_kernel(const float* __restrict__ X) {
    __shared__ float ks[16 * 64];
    __shared__ float vs[16 * 64];

    int blk = blockIdx.x;
    int split = blk & 7;
    int head  = (blk >> 3) & 7;
    int b     = blk >> 6;
    int t  = threadIdx.x;
    int tx = t & 15;
    int ty = t >> 4;

    float acc[4][4];
#pragma unroll
    for (int i = 0; i < 4; i++)
#pragma unroll
        for (int j = 0; j < 4; j++) acc[i][j] = 0.0f;

    int n_base = split * 512;
    for (int c0 = 0; c0 < 512; c0 += 16) {
        int n0 = n_base + c0;
#pragma unroll
        for (int rep = 0; rep < 2; rep++) {
            int p = t + rep * 256;
            int row = p >> 5;
            int jl  = p & 31;
            int pos = n0 + row;
            float2 kv2 = *(const float2*)(g_kf +
                ((size_t)(b * NPOS + pos)) * 512 + head * 64 + 2 * jl);
            int jg = head * 32 + jl;
            float cc = g_cos[pos * 256 + jg];
            float ss = g_sin[pos * 256 + jg];
            ks[row * 64 + 2 * jl]     = cc * kv2.x - ss * kv2.y;
            ks[row * 64 + 2 * jl + 1] = cc * kv2.y + ss * kv2.x;
        }
        {
            int row = t >> 4;
            int c4 = (t & 15) * 4;
            *(float4*)&vs[row * 64 + c4] = *(const float4*)(X +
                ((size_t)(b * NPOS + n0 + row)) * 512 + head * 64 + c4);
        }
        __syncthreads();

#pragma unroll
        for (int kk = 0; kk < 16; kk++) {
            float a[4], bb[4];
            *(float4*)a  = *(const float4*)&ks[kk * 64 + ty * 4];
            *(float4*)bb = *(const float4*)&vs[kk * 64 + tx * 4];
#pragma unroll
            for (int i = 0; i < 4; i++)
#pragma unroll
                for (int j = 0; j < 4; j++)
                    acc[i][j] = fmaf(a[i], bb[j], acc[i][j]);
        }
        __syncthreads();
    }

    float* kvp = g_kv + (b * 8 + head) * 4096;
#pragma unroll
    for (int i = 0; i < 4; i++)
#pragma unroll
        for (int j = 0; j < 4; j++)
            atomicAdd(&kvp[(ty * 4 + i) * 64 + tx * 4 + j],
                      acc[i][j] * (1.0f / 4096.0f));
}

// -------- K4: out = (rope(q) @ kv) * z,  z = 1/(q . kmean + 1e-6) --------
__global__ __launch_bounds__(256) void out_kernel(float* __restrict__ out) {
    __shared__ float kvs[64 * 64];
    __shared__ float qs[64 * 65];
    __shared__ float zarr[64];
    __shared__ float km[64];

    int blk = blockIdx.x;
    int pchunk = blk & 63;
    int head   = (blk >> 6) & 7;
    int b      = blk >> 9;
    int n0 = pchunk * 64;
    int t = threadIdx.x;

    const float* kvp = g_kv + (b * 8 + head) * 4096;
    for (int i = t; i < 4096; i += 256) kvs[i] = kvp[i];
    if (t < 64) km[t] = g_ksum[b * 512 + head * 64 + t] * (1.0f / 4096.0f);

    {
        int pos = t >> 2;
        int cb = (t & 3) * 16;
        const float* src = g_qf + ((size_t)(b * NPOS + n0 + pos)) * 512 + head * 64 + cb;
        float* dq = &qs[pos * 65 + cb];
#pragma unroll
        for (int u = 0; u < 16; u += 4) {
            float4 v = *(const float4*)(src + u);
            dq[u + 0] = v.x; dq[u + 1] = v.y; dq[u + 2] = v.z; dq[u + 3] = v.w;
        }
    }
    __syncthreads();

    if (t < 64) {
        float dot = 0.0f;
#pragma unroll
        for (int d2 = 0; d2 < 64; d2++) dot = fmaf(qs[t * 65 + d2], km[d2], dot);
        zarr[t] = 1.0f / (dot + 1e-6f);
    }
    __syncthreads();

#pragma unroll
    for (int rep = 0; rep < 8; rep++) {
        int p = t + rep * 256;
        int pos = p >> 5;
        int jl  = p & 31;
        float re = qs[pos * 65 + 2 * jl];
        float im = qs[pos * 65 + 2 * jl + 1];
        int gp = (n0 + pos) * 256 + head * 32 + jl;
        float cc = g_cos[gp];
        float ss = g_sin[gp];
        qs[pos * 65 + 2 * jl]     = cc * re - ss * im;
        qs[pos * 65 + 2 * jl + 1] = cc * im + ss * re;
    }
    __syncthreads();

    int e = t & 63;
    for (int it = 0; it < 16; it++) {
        int pos = it * 4 + (t >> 6);
        float a2 = 0.0f;
#pragma unroll
        for (int d2 = 0; d2 < 64; d2++)
            a2 = fmaf(qs[pos * 65 + d2], kvs[d2 * 64 + e], a2);
        out[((size_t)(b * NPOS + n0 + pos)) * 512 + head * 64 + e] = a2 * zarr[pos];
    }
}

// -------- K5: LePE depthwise 3x3 conv on x, added into out --------
__global__ void lepe_kernel(const float* __restrict__ X,
                            const float* __restrict__ Wc,
                            const float* __restrict__ Bc,
                            float* __restrict__ out) {
    int idx = blockIdx.x * blockDim.x + threadIdx.x;
    int ch  = idx & 511;
    int rest = idx >> 9;
    int pos = rest & 4095;
    int b = rest >> 12;
    int hi = pos >> 6;
    int wi = pos & 63;

    float acc = Bc[ch];
    const float* wp = Wc + ch * 9;
    const float* xb = X + ((size_t)b * NPOS) * 512 + ch;
#pragma unroll
    for (int ky = 0; ky < 3; ky++) {
        int y = hi + ky - 1;
        if ((unsigned)y >= 64u) continue;
#pragma unroll
        for (int kx = 0; kx < 3; kx++) {
            int xw = wi + kx - 1;
            if ((unsigned)xw >= 64u) continue;
            acc = fmaf(xb[((size_t)(y * 64 + xw)) * 512], wp[ky * 3 + kx], acc);
        }
    }
    out[idx] += acc;
}

// -------- launch --------
extern "C" void kernel_launch(void* const* d_in, const int* in_sizes, int n_in,
                              void* d_out, int out_size) {
    const float* x   = nullptr;
    const float* Wqk = nullptr;
    const float* bqk = nullptr;
    const float* lw  = nullptr;
    const float* lb  = nullptr;
    for (int i = 0; i < n_in; i++) {
        switch (in_sizes[i]) {
            case 16777216: x   = (const float*)d_in[i]; break;  // x (8,4096,512)
            case 524288:   Wqk = (const float*)d_in[i]; break;  // (1024,512)
            case 1024:     bqk = (const float*)d_in[i]; break;
            case 4608:     lw  = (const float*)d_in[i]; break;  // (512,1,3,3)
            case 512:      lb  = (const float*)d_in[i]; break;
            default: break;
        }
    }
    float* out = (float*)d_out;

    zero_kernel<<<1024, 256>>>();
    rope_table_kernel<<<NPOS, 256>>>();
    gemm_qk_bf16_kernel<<<dim3(8, 256), 256>>>(x, Wqk, bqk);
    ksum_kernel<<<BATCH * 32, 512>>>();
    kv_kernel<<<BATCH * HEADS * 8, 256>>>(x);
    out_kernel<<<BATCH * HEADS * 64, 256>>>(out);
    lepe_kernel<<<(BATCH * NPOS * CCH) / 256, 256>>>(x, lw, lb, out);
}